// round 1
// baseline (speedup 1.0000x reference)
#include <cuda_runtime.h>
#include <math.h>

#define N_  4
#define C_  128
#define H_  128
#define W_  128
#define HW_ 16384
#define L_  65536
#define G_  4
#define K_  9
#define CG_ 32
#define VSTRIDE 256

// Scratch (device globals; no allocation allowed)
__device__ __align__(16) float g_valom[(size_t)L_ * VSTRIDE];   // 64 MB: value cols 0..127, om cols 128..239
__device__ __align__(16) float g_wpad[256 * 128];               // folded weights [o][c]
__device__ __align__(16) float g_bpad[256];                     // folded biases
__device__ __align__(16) float g_outwT[128 * 128];              // out_w transposed [c][o]

// ---------------------------------------------------------------------------
// Kernel 0: fold value_w/om_w through conv_w, fold biases, transpose out_w.
// grid(256) x block(128)
// ---------------------------------------------------------------------------
__global__ void prep_kernel(const float* __restrict__ conv_w, const float* __restrict__ conv_b,
                            const float* __restrict__ value_w, const float* __restrict__ value_b,
                            const float* __restrict__ om_w, const float* __restrict__ om_b,
                            const float* __restrict__ out_w) {
    int o = blockIdx.x;    // 0..255
    int c = threadIdx.x;   // 0..127
    __shared__ float srow[128];
    __shared__ float red[128];

    const float* src = nullptr;
    float extra_b = 0.f;
    if (o < 128)      { src = value_w + o * 128;      extra_b = value_b[o]; }
    else if (o < 240) { src = om_w + (o - 128) * 128; extra_b = om_b[o - 128]; }

    srow[c] = src ? src[c] : 0.f;
    __syncthreads();

    float acc = 0.f;
#pragma unroll 8
    for (int m = 0; m < 128; m++) acc += srow[m] * conv_w[m * 128 + c];
    g_wpad[o * 128 + c] = acc;

    red[c] = srow[c] * conv_b[c];
    __syncthreads();
    for (int s = 64; s > 0; s >>= 1) {
        if (c < s) red[c] += red[c + s];
        __syncthreads();
    }
    if (c == 0) g_bpad[o] = red[0] + extra_b;

    if (o < 128) g_outwT[c * 128 + o] = out_w[o * 128 + c];
}

// ---------------------------------------------------------------------------
// Kernel 1: valom = X_tokens(65536x128) @ Wpad^T(128x256) + bpad
// X token l=(n,hw): A[l][c] = x[n*C*HW + c*HW + hw]  (coalesced along hw)
// grid(512, 2) x block(256). 128x128 tile, 8x8 per thread.
// ---------------------------------------------------------------------------
__global__ __launch_bounds__(256, 2) void gemm_valom(const float* __restrict__ x) {
    __shared__ __align__(16) float As[32][128];
    __shared__ float Bs[32][129];   // padded: conflict-free stores & reads

    int l0 = blockIdx.x * 128;
    int o0 = blockIdx.y * 128;
    int n = l0 >> 14;
    int hw0 = l0 & (HW_ - 1);
    const float* xb = x + (size_t)n * C_ * HW_ + hw0;

    int tid = threadIdx.x;
    int tx = tid & 15, ty = tid >> 4;

    float acc[8][8];
#pragma unroll
    for (int i = 0; i < 8; i++)
#pragma unroll
        for (int j = 0; j < 8; j++) acc[i][j] = 0.f;

    for (int kk = 0; kk < 128; kk += 32) {
#pragma unroll
        for (int i = 0; i < 16; i++) {
            int idx = tid + i * 256;
            int mi = idx & 127, ki = idx >> 7;
            As[ki][mi] = xb[(size_t)(kk + ki) * HW_ + mi];
        }
#pragma unroll
        for (int i = 0; i < 4; i++) {
            int idx = tid + i * 256;        // 1024 float4 loads total
            int kq = idx & 7, oi = idx >> 3;
            float4 v = *(const float4*)&g_wpad[(o0 + oi) * 128 + kk + kq * 4];
            Bs[kq * 4 + 0][oi] = v.x;
            Bs[kq * 4 + 1][oi] = v.y;
            Bs[kq * 4 + 2][oi] = v.z;
            Bs[kq * 4 + 3][oi] = v.w;
        }
        __syncthreads();

#pragma unroll
        for (int ki = 0; ki < 32; ki++) {
            float a[8], b[8];
            float4 a0 = *(const float4*)&As[ki][ty * 8];
            float4 a1 = *(const float4*)&As[ki][ty * 8 + 4];
            a[0] = a0.x; a[1] = a0.y; a[2] = a0.z; a[3] = a0.w;
            a[4] = a1.x; a[5] = a1.y; a[6] = a1.z; a[7] = a1.w;
#pragma unroll
            for (int j = 0; j < 8; j++) b[j] = Bs[ki][tx * 8 + j];
#pragma unroll
            for (int i = 0; i < 8; i++)
#pragma unroll
                for (int j = 0; j < 8; j++) acc[i][j] += a[i] * b[j];
        }
        __syncthreads();
    }

#pragma unroll
    for (int i = 0; i < 8; i++) {
        int l = l0 + ty * 8 + i;
        float* dst = &g_valom[(size_t)l * VSTRIDE + o0 + tx * 8];
#pragma unroll
        for (int j = 0; j < 8; j++) dst[j] = acc[i][j] + g_bpad[o0 + tx * 8 + j];
    }
}

// ---------------------------------------------------------------------------
// Kernel 2: DCNv4 core + output GEMM + NCHW transposed store.
// grid(2048) x block(256). Block = 32 consecutive tokens (one h row segment).
// DCN: warp owns (token,group) pair; lane = channel within group (coalesced 128B gathers).
// GEMM: y[t][o] = sum_c out[t][c]*outwT[c][o], outwT staged via shared chunks.
// ---------------------------------------------------------------------------
__global__ __launch_bounds__(256, 4) void dcn_out_kernel(const float* __restrict__ out_b,
                                                          float* __restrict__ y) {
    // unioned region: om (32x112) / w-chunk (32x128) / y-stage (32x129)
    __shared__ __align__(16) float sm1[32 * 130];
    __shared__ __align__(16) float s_out[32][128];

    int tid = threadIdx.x;
    int l0 = blockIdx.x * 32;
    int n = l0 >> 14;
    int hw0 = l0 & (HW_ - 1);
    int h = hw0 >> 7;      // same row for all 32 tokens
    int w0 = hw0 & 127;

    // load om (108 used of 112) for 32 tokens
    for (int idx = tid; idx < 32 * 112; idx += 256) {
        int t = idx / 112, j = idx - t * 112;
        sm1[t * 112 + j] = g_valom[(size_t)(l0 + t) * VSTRIDE + 128 + j];
    }
    __syncthreads();

    int warp = tid >> 5, lane = tid & 31;
    const float* vbase = g_valom + (size_t)n * HW_ * VSTRIDE;

    // DCN core: 8 warps x 16 (token,group) pairs
    for (int i = 0; i < 16; i++) {
        int p = warp * 16 + i;
        int t = p >> 2, g = p & 3;
        const float* om = &sm1[t * 112 + g * 27];
        int w = w0 + t;
        const float* vg = vbase + g * 32 + lane;
        float acc = 0.f;
#pragma unroll
        for (int k = 0; k < 9; k++) {
            float offx = om[2 * k], offy = om[2 * k + 1], m = om[18 + k];
            float px = (float)(w + (k % 3) - 1) + offx;
            float py = (float)(h + (k / 3) - 1) + offy;
            float x0f = floorf(px), y0f = floorf(py);
            float lx = px - x0f, ly = py - y0f;
            int x0 = (int)x0f, y0 = (int)y0f;
            int x1 = x0 + 1, y1 = y0 + 1;
            float s = 0.f;
            if (x0 >= 0 && x0 < W_ && y0 >= 0 && y0 < H_)
                s += (1.f - lx) * (1.f - ly) * vg[(size_t)(y0 * W_ + x0) * VSTRIDE];
            if (x1 >= 0 && x1 < W_ && y0 >= 0 && y0 < H_)
                s += lx * (1.f - ly) * vg[(size_t)(y0 * W_ + x1) * VSTRIDE];
            if (x0 >= 0 && x0 < W_ && y1 >= 0 && y1 < H_)
                s += (1.f - lx) * ly * vg[(size_t)(y1 * W_ + x0) * VSTRIDE];
            if (x1 >= 0 && x1 < W_ && y1 >= 0 && y1 < H_)
                s += lx * ly * vg[(size_t)(y1 * W_ + x1) * VSTRIDE];
            acc += m * s;
        }
        s_out[t][g * 32 + lane] = acc;
    }
    __syncthreads();

    // output GEMM
    int tx = tid & 15, ty = tid >> 4;
    float accy[2][8];
#pragma unroll
    for (int s = 0; s < 2; s++)
#pragma unroll
        for (int j = 0; j < 8; j++) accy[s][j] = 0.f;

    for (int c0 = 0; c0 < 128; c0 += 32) {
        __syncthreads();   // protect sm1 reuse
        for (int idx4 = tid; idx4 < 1024; idx4 += 256)
            *(float4*)&sm1[idx4 * 4] = *(const float4*)&g_outwT[c0 * 128 + idx4 * 4];
        __syncthreads();
#pragma unroll
        for (int ci = 0; ci < 32; ci++) {
            float b[8];
            float4 b0 = *(const float4*)&sm1[ci * 128 + tx * 8];
            float4 b1 = *(const float4*)&sm1[ci * 128 + tx * 8 + 4];
            b[0] = b0.x; b[1] = b0.y; b[2] = b0.z; b[3] = b0.w;
            b[4] = b1.x; b[5] = b1.y; b[6] = b1.z; b[7] = b1.w;
            float a0 = s_out[ty * 2][c0 + ci];
            float a1 = s_out[ty * 2 + 1][c0 + ci];
#pragma unroll
            for (int j = 0; j < 8; j++) {
                accy[0][j] += a0 * b[j];
                accy[1][j] += a1 * b[j];
            }
        }
    }
    __syncthreads();

    // stage y (stride 129 -> conflict-free transposed read) + bias
#pragma unroll
    for (int s = 0; s < 2; s++) {
        int t = ty * 2 + s;
#pragma unroll
        for (int j = 0; j < 8; j++) {
            int o = tx * 8 + j;
            sm1[t * 129 + o] = accy[s][j] + out_b[o];
        }
    }
    __syncthreads();

    // coalesced NCHW store: lanes span w
    for (int idx = tid; idx < 4096; idx += 256) {
        int o = idx >> 5, t = idx & 31;
        y[((size_t)(n * C_ + o) << 14) + hw0 + t] = sm1[t * 129 + o];
    }
}

// ---------------------------------------------------------------------------
extern "C" void kernel_launch(void* const* d_in, const int* in_sizes, int n_in,
                              void* d_out, int out_size) {
    const float* x       = (const float*)d_in[0];
    const float* conv_w  = (const float*)d_in[1];
    const float* conv_b  = (const float*)d_in[2];
    const float* value_w = (const float*)d_in[3];
    const float* value_b = (const float*)d_in[4];
    const float* om_w    = (const float*)d_in[5];
    const float* om_b    = (const float*)d_in[6];
    const float* out_w   = (const float*)d_in[7];
    const float* out_b   = (const float*)d_in[8];
    float* y = (float*)d_out;

    prep_kernel<<<256, 128>>>(conv_w, conv_b, value_w, value_b, om_w, om_b, out_w);
    dim3 g1(512, 2);
    gemm_valom<<<g1, 256>>>(x);
    dcn_out_kernel<<<2048, 256>>>(out_b, y);
}

// round 5
// speedup vs baseline: 1.5197x; 1.5197x over previous
#include <cuda_runtime.h>
#include <math.h>
#include <stdint.h>

#define N_  4
#define C_  128
#define H_  128
#define W_  128
#define HW_ 16384
#define L_  65536
#define G_  4
#define K_  9

// ---------------- device scratch (no allocation allowed) -------------------
__device__ __align__(16) float g_value[(size_t)L_ * 128];  // 32 MB value tokens [t][c]
__device__ __align__(16) float g_om[(size_t)L_ * 128];     // 32 MB offset/mask [t][0..111]
__device__ __align__(16) float g_wpadT[128 * 256];         // folded weights^T [c][o], tf32 bits
__device__ __align__(16) float g_bpad[256];                // folded biases (fp32)
__device__ __align__(16) float g_outwT[128 * 128];         // out_w^T [c][o], tf32 bits

// ---------------- helpers ---------------------------------------------------
// tf32 round: destination of cvt.rna.tf32.f32 must be a b32 register.
__device__ __forceinline__ uint32_t tf32r(float x) {
    uint32_t y;
    asm("cvt.rna.tf32.f32 %0, %1;" : "=r"(y) : "f"(x));
    return y;
}
__device__ __forceinline__ float tf32f(float x) { return __uint_as_float(tf32r(x)); }

// D += A(16x8, row) x B(8x8, col), tf32 in, f32 accum.
__device__ __forceinline__ void mma_tf32(float* d, const uint32_t* a, const uint32_t* b) {
    asm volatile(
        "mma.sync.aligned.m16n8k8.row.col.f32.tf32.tf32.f32 "
        "{%0,%1,%2,%3}, {%4,%5,%6,%7}, {%8,%9}, {%0,%1,%2,%3};"
        : "+f"(d[0]), "+f"(d[1]), "+f"(d[2]), "+f"(d[3])
        : "r"(a[0]), "r"(a[1]), "r"(a[2]), "r"(a[3]), "r"(b[0]), "r"(b[1]));
}

// ---------------------------------------------------------------------------
// Kernel 0: fold value_w/om_w through conv_w; fold biases; transpose out_w.
// grid(256) x block(256)
// ---------------------------------------------------------------------------
__global__ void prep_kernel(const float* __restrict__ conv_w, const float* __restrict__ conv_b,
                            const float* __restrict__ value_w, const float* __restrict__ value_b,
                            const float* __restrict__ om_w, const float* __restrict__ om_b,
                            const float* __restrict__ out_w) {
    int o = blockIdx.x;
    int tid = threadIdx.x;
    int c = tid & 127, half = tid >> 7;
    __shared__ float srow[128];
    __shared__ float part[256];

    const float* src = nullptr;
    float extra_b = 0.f;
    if (o < 128)      { src = value_w + o * 128;      extra_b = value_b[o]; }
    else if (o < 240) { src = om_w + (o - 128) * 128; extra_b = om_b[o - 128]; }

    if (half == 0) srow[c] = src ? src[c] : 0.f;
    __syncthreads();

    float acc = 0.f;
    int m0 = half * 64;
#pragma unroll 8
    for (int m = 0; m < 64; m++) acc += srow[m0 + m] * conv_w[(m0 + m) * 128 + c];
    part[tid] = acc;
    __syncthreads();
    if (half == 0) g_wpadT[c * 256 + o] = tf32f(part[c] + part[c + 128]);

    if (tid < 32) {
        float s = 0.f;
#pragma unroll
        for (int j = 0; j < 4; j++) s += srow[tid + 32 * j] * conv_b[tid + 32 * j];
#pragma unroll
        for (int sh = 16; sh > 0; sh >>= 1) s += __shfl_xor_sync(0xffffffffu, s, sh);
        if (tid == 0) g_bpad[o] = s + extra_b;
    }

    if (o < 128 && half == 0) g_outwT[c * 128 + o] = tf32f(out_w[o * 128 + c]);
}

// ---------------------------------------------------------------------------
// Kernel 1: mma.sync tf32 GEMM.  out[t][o] = sum_c X[t][c] * Wpad[o][c]
// grid(512, 2): x = 128-token tile, y = o-half (0: value, 1: om). block 256.
// SMEM: buf[128*132] floats; As = rows 0..63 (k-chunk), Bs = rows 64..127.
// After compute, buf reused as D-stage [128 tokens][132].
// ---------------------------------------------------------------------------
#define STR 132
#define VAL_SMEM (128 * STR * 4)

__global__ __launch_bounds__(256) void mma_valom(const float* __restrict__ x) {
    extern __shared__ float buf[];
    float* As = buf;                // [64][STR]  As[k][m]
    float* Bs = buf + 64 * STR;     // [64][STR]  Bs[k][n]

    int tid = threadIdx.x;
    int wid = tid >> 5, lane = tid & 31;
    int g8 = lane >> 2, tig = lane & 3;   // groupID, threadID_in_group
    int l0 = blockIdx.x * 128;
    int o0 = blockIdx.y * 128;
    int n = l0 >> 14, hw0 = l0 & (HW_ - 1);
    const float* xb = x + (size_t)n * C_ * HW_ + hw0;

    int m_base = (wid & 3) * 32;
    int n_base = (wid >> 2) * 64;

    float d[2][8][4];
#pragma unroll
    for (int mi = 0; mi < 2; mi++)
#pragma unroll
        for (int ni = 0; ni < 8; ni++)
#pragma unroll
            for (int r = 0; r < 4; r++) d[mi][ni][r] = 0.f;

    for (int ch = 0; ch < 2; ch++) {
        int kg = ch * 64;
        // fill As: x tokens (tf32-rounded), As[c][t]
#pragma unroll
        for (int i = 0; i < 8; i++) {
            int c = wid + 8 * i;
            float4 v = *(const float4*)(xb + (size_t)(kg + c) * HW_ + 4 * lane);
            v.x = tf32f(v.x); v.y = tf32f(v.y); v.z = tf32f(v.z); v.w = tf32f(v.w);
            *(float4*)&As[c * STR + 4 * lane] = v;
        }
        // fill Bs: folded weights^T (already tf32), Bs[c][o]
#pragma unroll
        for (int i = 0; i < 8; i++) {
            int c = wid + 8 * i;
            float4 v = *(const float4*)&g_wpadT[(size_t)(kg + c) * 256 + o0 + 4 * lane];
            *(float4*)&Bs[c * STR + 4 * lane] = v;
        }
        __syncthreads();

#pragma unroll
        for (int ks = 0; ks < 8; ks++) {
            int kk = ks * 8;
            uint32_t a[2][4], b[8][2];
#pragma unroll
            for (int mi = 0; mi < 2; mi++) {
                int m0 = m_base + 16 * mi + g8;
                a[mi][0] = __float_as_uint(As[(kk + tig) * STR + m0]);
                a[mi][1] = __float_as_uint(As[(kk + tig) * STR + m0 + 8]);
                a[mi][2] = __float_as_uint(As[(kk + tig + 4) * STR + m0]);
                a[mi][3] = __float_as_uint(As[(kk + tig + 4) * STR + m0 + 8]);
            }
#pragma unroll
            for (int ni = 0; ni < 8; ni++) {
                int nn = n_base + 8 * ni + g8;
                b[ni][0] = __float_as_uint(Bs[(kk + tig) * STR + nn]);
                b[ni][1] = __float_as_uint(Bs[(kk + tig + 4) * STR + nn]);
            }
#pragma unroll
            for (int mi = 0; mi < 2; mi++)
#pragma unroll
                for (int ni = 0; ni < 8; ni++) mma_tf32(d[mi][ni], a[mi], b[ni]);
        }
        __syncthreads();
    }

    // stage D into buf[t][o] (stride 132)
#pragma unroll
    for (int mi = 0; mi < 2; mi++) {
        int m0 = m_base + 16 * mi + g8;
#pragma unroll
        for (int ni = 0; ni < 8; ni++) {
            int oo = n_base + 8 * ni + 2 * tig;
            buf[m0 * STR + oo]           = d[mi][ni][0];
            buf[m0 * STR + oo + 1]       = d[mi][ni][1];
            buf[(m0 + 8) * STR + oo]     = d[mi][ni][2];
            buf[(m0 + 8) * STR + oo + 1] = d[mi][ni][3];
        }
    }
    __syncthreads();

    // coalesced store + bias
    float4 bias = *(const float4*)&g_bpad[o0 + 4 * lane];
    float* dst = (blockIdx.y == 0 ? g_value : g_om) + (size_t)l0 * 128;
#pragma unroll
    for (int i = 0; i < 16; i++) {
        int t = wid + 8 * i;
        float4 v = *(const float4*)&buf[t * STR + 4 * lane];
        v.x += bias.x; v.y += bias.y; v.z += bias.z; v.w += bias.w;
        *(float4*)(dst + (size_t)t * 128 + 4 * lane) = v;
    }
}

// ---------------------------------------------------------------------------
// Kernel 2: DCNv4 core + mma.sync output GEMM + NCHW transposed store.
// grid(2048) x block(256). Block = 32 consecutive tokens (one h-row segment).
// Dyn smem: s_a[32*132] (dcn out, tf32) | s_b[32*132] (w chunk) | s_c[32*132] (om -> y stage)
// ---------------------------------------------------------------------------
#define DCN_SMEM (3 * 32 * STR * 4)

__global__ __launch_bounds__(256) void dcn_out_kernel(const float* __restrict__ out_b,
                                                      float* __restrict__ y) {
    extern __shared__ float sm[];
    float* s_a = sm;                 // [32][STR] dcn output (A operand)
    float* s_b = sm + 32 * STR;      // [32][STR] outwT chunk (B operand)
    float* s_c = sm + 64 * STR;      // om stage, then y stage (stride 129)

    int tid = threadIdx.x;
    int warp = tid >> 5, lane = tid & 31;
    int g8 = lane >> 2, tig = lane & 3;
    int l0 = blockIdx.x * 32;
    int n = l0 >> 14;
    int hw0 = l0 & (HW_ - 1);
    int h = hw0 >> 7;
    int w0 = hw0 & 127;

    // stage om (112 floats per token)
    for (int idx4 = tid; idx4 < 896; idx4 += 256) {
        int t = idx4 / 28, j = idx4 - t * 28;
        float4 v = *(const float4*)&g_om[(size_t)(l0 + t) * 128 + 4 * j];
        *(float4*)&s_c[t * 112 + 4 * j] = v;
    }
    __syncthreads();

    const float* vbase = g_value + (size_t)n * HW_ * 128;

    // DCN core: warp handles 16 (token,group) pairs; lane = channel in group
    for (int i = 0; i < 16; i++) {
        int p = warp * 16 + i;
        int t = p >> 2, g = p & 3;
        const float* om = &s_c[t * 112 + g * 27];
        int w = w0 + t;
        const float* vg = vbase + g * 32 + lane;
        float acc = 0.f;
#pragma unroll
        for (int k = 0; k < 9; k++) {
            float offx = om[2 * k], offy = om[2 * k + 1], m = om[18 + k];
            float px = (float)(w + (k % 3) - 1) + offx;
            float py = (float)(h + (k / 3) - 1) + offy;
            float x0f = floorf(px), y0f = floorf(py);
            float lx = px - x0f, ly = py - y0f;
            int x0 = (int)x0f, y0 = (int)y0f;
            int x1 = x0 + 1, y1 = y0 + 1;
            float vx0 = (x0 >= 0 && x0 < W_) ? 1.f : 0.f;
            float vx1 = (x1 >= 0 && x1 < W_) ? 1.f : 0.f;
            float vy0 = (y0 >= 0 && y0 < H_) ? 1.f : 0.f;
            float vy1 = (y1 >= 0 && y1 < H_) ? 1.f : 0.f;
            int xc0 = min(max(x0, 0), W_ - 1), xc1 = min(max(x1, 0), W_ - 1);
            int yc0 = min(max(y0, 0), H_ - 1), yc1 = min(max(y1, 0), H_ - 1);
            const float* r0 = vg + (size_t)(yc0 * W_) * 128;
            const float* r1 = vg + (size_t)(yc1 * W_) * 128;
            float v00 = r0[(size_t)xc0 * 128];
            float v01 = r0[(size_t)xc1 * 128];
            float v10 = r1[(size_t)xc0 * 128];
            float v11 = r1[(size_t)xc1 * 128];
            float w00 = (1.f - lx) * (1.f - ly) * vx0 * vy0;
            float w01 = lx * (1.f - ly) * vx1 * vy0;
            float w10 = (1.f - lx) * ly * vx0 * vy1;
            float w11 = lx * ly * vx1 * vy1;
            acc += m * (w00 * v00 + w01 * v01 + w10 * v10 + w11 * v11);
        }
        s_a[t * STR + g * 32 + lane] = tf32f(acc);
    }

    // output GEMM via mma: C[t][o] = sum_c s_a[t][c] * outwT[c][o]
    int m_base = (warp & 1) * 16;
    int n_base = (warp >> 1) * 32;
    float d[4][4];
#pragma unroll
    for (int ni = 0; ni < 4; ni++)
#pragma unroll
        for (int r = 0; r < 4; r++) d[ni][r] = 0.f;

    for (int c0 = 0; c0 < 128; c0 += 32) {
        __syncthreads();
#pragma unroll
        for (int i = 0; i < 4; i++) {
            int c = warp + 8 * i;
            float4 v = *(const float4*)&g_outwT[(size_t)(c0 + c) * 128 + 4 * lane];
            *(float4*)&s_b[c * STR + 4 * lane] = v;
        }
        __syncthreads();
#pragma unroll
        for (int ks = 0; ks < 4; ks++) {
            int kk = 8 * ks;
            uint32_t a[4], b[4][2];
            int m0 = m_base + g8;
            a[0] = __float_as_uint(s_a[m0 * STR + c0 + kk + tig]);
            a[1] = __float_as_uint(s_a[(m0 + 8) * STR + c0 + kk + tig]);
            a[2] = __float_as_uint(s_a[m0 * STR + c0 + kk + tig + 4]);
            a[3] = __float_as_uint(s_a[(m0 + 8) * STR + c0 + kk + tig + 4]);
#pragma unroll
            for (int ni = 0; ni < 4; ni++) {
                int nn = n_base + 8 * ni + g8;
                b[ni][0] = __float_as_uint(s_b[(kk + tig) * STR + nn]);
                b[ni][1] = __float_as_uint(s_b[(kk + tig + 4) * STR + nn]);
            }
#pragma unroll
            for (int ni = 0; ni < 4; ni++) mma_tf32(d[ni], a, b[ni]);
        }
    }
    __syncthreads();

    // y stage (stride 129) + bias
#pragma unroll
    for (int ni = 0; ni < 4; ni++) {
        int oo = n_base + 8 * ni + 2 * tig;
        float2 bb = *(const float2*)&out_b[oo];
        int t0 = m_base + g8;
        s_c[t0 * 129 + oo]           = d[ni][0] + bb.x;
        s_c[t0 * 129 + oo + 1]       = d[ni][1] + bb.y;
        s_c[(t0 + 8) * 129 + oo]     = d[ni][2] + bb.x;
        s_c[(t0 + 8) * 129 + oo + 1] = d[ni][3] + bb.y;
    }
    __syncthreads();

    // coalesced NCHW store: lanes span w
#pragma unroll
    for (int i = 0; i < 16; i++) {
        int o = warp + 8 * i;
        y[((size_t)(n * C_ + o) << 14) + hw0 + lane] = s_c[lane * 129 + o];
    }
}

// ---------------------------------------------------------------------------
extern "C" void kernel_launch(void* const* d_in, const int* in_sizes, int n_in,
                              void* d_out, int out_size) {
    const float* x       = (const float*)d_in[0];
    const float* conv_w  = (const float*)d_in[1];
    const float* conv_b  = (const float*)d_in[2];
    const float* value_w = (const float*)d_in[3];
    const float* value_b = (const float*)d_in[4];
    const float* om_w    = (const float*)d_in[5];
    const float* om_b    = (const float*)d_in[6];
    const float* out_w   = (const float*)d_in[7];
    const float* out_b   = (const float*)d_in[8];
    float* y = (float*)d_out;

    cudaFuncSetAttribute(mma_valom, cudaFuncAttributeMaxDynamicSharedMemorySize, VAL_SMEM);
    cudaFuncSetAttribute(dcn_out_kernel, cudaFuncAttributeMaxDynamicSharedMemorySize, DCN_SMEM);

    prep_kernel<<<256, 256>>>(conv_w, conv_b, value_w, value_b, om_w, om_b, out_w);
    dim3 g1(512, 2);
    mma_valom<<<g1, 256, VAL_SMEM>>>(x);
    dcn_out_kernel<<<2048, 256, DCN_SMEM>>>(out_b, y);
}